// round 6
// baseline (speedup 1.0000x reference)
#include <cuda_runtime.h>
#include <cstdint>

#define BATCH 16
#define ECH 32
#define NCLS 3
#define HW 262144           // 512*512
#define CHUNK_PX 32
#define NCHUNK (HW/CHUNK_PX)   // 8192 chunks per image
#define GX 28                  // grid (28,16) = 448 CTAs ~= 3/SM on 152 SMs
#define NBLK (GX*BATCH)        // 448
#define NWSLOT (GX*8)          // 224 warp-slots per image
#define RSTRIDE 36             // floats per channel row (mod 32 == 4 -> conflict-free)

// per-warp smem: 2 bufs of [ECH][RSTRIDE] + 2 meta[32]
#define BUF_FLOATS (ECH*RSTRIDE)          // 1152
#define WARP_FLOATS (2*BUF_FLOATS + 64)   // 2368
#define SM_FLOATS (8*WARP_FLOATS)         // 18944
#define SMEM_BYTES (SM_FLOATS*4)          // 75776 -> 3 CTAs/SM

// per-block partial results (unique slots -> no zeroing, no atomics on data)
__device__ float g_part[BATCH][GX][4][ECH]; // [0]=sum_emb_l1 [1]=sum_hat_l1 [2]=sum_emb_l2 [3]=sum_hat_l2
__device__ float g_misc[BATCH][GX][3];      // ce, c1, c2
__device__ unsigned int g_sync;             // zero-init; atomicInc wraps -> graph-replay safe

__device__ __forceinline__ void cp16(uint32_t dst, const float* src) {
    asm volatile("cp.async.cg.shared.global [%0], [%1], 16;" :: "r"(dst), "l"(src));
}
__device__ __forceinline__ void cp_commit() {
    asm volatile("cp.async.commit_group;" ::: "memory");
}
__device__ __forceinline__ void cp_wait1() {
    asm volatile("cp.async.wait_group 1;" ::: "memory");
}

__global__ __launch_bounds__(256, 3)
void main_kernel(const float* __restrict__ emb,
                 const float* __restrict__ pred,
                 const int*  __restrict__ lab,
                 const int*  __restrict__ nb,
                 float* __restrict__ out) {
    extern __shared__ float sm[];

    const int b    = blockIdx.y;
    const int tid  = threadIdx.x;
    const int wid  = tid >> 5;
    const int lane = tid & 31;
    const int gw0  = blockIdx.x * 8 + wid;     // warp-slot in [0, NWSLOT)

    float* wbase = sm + wid * WARP_FLOATS;
    const uint32_t wbase_u = (uint32_t)__cvta_generic_to_shared(wbase);

    const float* embB  = emb  + (size_t)b * ECH  * HW;
    const float* predB = pred + (size_t)b * NCLS * HW;
    const int*   labB  = lab  + (size_t)b * HW;

    const int erow = lane >> 3;   // base channel group 0..3
    const int seg  = lane & 7;    // 16B segment within 128B row

    // accumulators: a/h indexed by lane==channel; ce/c by lane==pixel-slot
    float a1 = 0.f, h1 = 0.f, a2 = 0.f, h2 = 0.f;
    float ce = 0.f;
    int   c1 = 0, c2 = 0;

    // two register sets for label/pred prefetch
    int   lb0 = 0, lb1 = 0;
    float p00 = 0.f, p01 = 0.f, p02 = 0.f;
    float p10 = 0.f, p11 = 0.f, p12 = 0.f;

    // ---- issue chunk j into buffer (j&1): 8 cp.async.128 + 4 small LDGs ----
    #define ISSUE(J, LB, PA, PB, PC) do {                                        \
        const int _c = gw0 + (J) * NWSLOT;                                       \
        if (_c < NCHUNK) {                                                       \
            const int _P = _c * CHUNK_PX;                                        \
            const float* _s = embB + (size_t)erow * HW + _P + seg * 4;           \
            uint32_t _d = wbase_u + ((J) & 1) * (BUF_FLOATS * 4)                 \
                          + erow * (RSTRIDE * 4) + seg * 16;                     \
            _Pragma("unroll")                                                    \
            for (int _q = 0; _q < 8; _q++)                                       \
                cp16(_d + _q * 4 * RSTRIDE * 4, _s + (size_t)_q * 4 * HW);       \
            LB = labB[_P + lane];                                                \
            PA = predB[_P + lane];                                               \
            PB = predB[HW + _P + lane];                                          \
            PC = predB[2 * HW + _P + lane];                                      \
        }                                                                        \
        cp_commit();                                                             \
    } while (0)

    // ---- process chunk in buffer (J&1) with given reg set ----
    #define PROCESS(J, LB, PA, PB, PC) do {                                      \
        cp_wait1();                                                              \
        __syncwarp();                                                            \
        float* _buf  = wbase + ((J) & 1) * BUF_FLOATS;                           \
        float* _meta = wbase + 2 * BUF_FLOATS + ((J) & 1) * 32;                  \
        float _sq = 0.f;                                                         \
        _Pragma("unroll")                                                        \
        for (int _k = 0; _k < ECH; _k++) {                                       \
            float _x = _buf[_k * RSTRIDE + lane];                                \
            _sq = fmaf(_x, _x, _sq);                                             \
        }                                                                        \
        float _r = 1.f / fmaxf(sqrtf(_sq), 1e-8f);                               \
        _meta[lane] = (LB == 1) ? _r : ((LB == 2) ? -_r : 0.f);                  \
        c1 += (LB == 1); c2 += (LB == 2);                                        \
        float _m = fmaxf(PA, fmaxf(PB, PC));                                     \
        ce += _m + __logf(__expf(PA - _m) + __expf(PB - _m) + __expf(PC - _m))   \
              - ((LB == 0) ? PA : ((LB == 1) ? PB : PC));                        \
        __syncwarp();                                                            \
        const float* _vrow = _buf + lane * RSTRIDE;                              \
        _Pragma("unroll")                                                        \
        for (int _k = 0; _k < 8; _k++) {                                         \
            float4 _w = *(const float4*)(_vrow + 4 * _k);                        \
            float4 _t = *(const float4*)(_meta + 4 * _k);                        \
            float _vh0 = _w.x * fabsf(_t.x);                                     \
            float _vh1 = _w.y * fabsf(_t.y);                                     \
            float _vh2 = _w.z * fabsf(_t.z);                                     \
            float _vh3 = _w.w * fabsf(_t.w);                                     \
            if      (_t.x > 0.f) { a1 += _w.x; h1 += _vh0; }                     \
            else if (_t.x < 0.f) { a2 += _w.x; h2 += _vh0; }                     \
            if      (_t.y > 0.f) { a1 += _w.y; h1 += _vh1; }                     \
            else if (_t.y < 0.f) { a2 += _w.y; h2 += _vh1; }                     \
            if      (_t.z > 0.f) { a1 += _w.z; h1 += _vh2; }                     \
            else if (_t.z < 0.f) { a2 += _w.z; h2 += _vh2; }                     \
            if      (_t.w > 0.f) { a1 += _w.w; h1 += _vh3; }                     \
            else if (_t.w < 0.f) { a2 += _w.w; h2 += _vh3; }                     \
        }                                                                        \
        __syncwarp();                                                            \
    } while (0)

    // prologue: two chunks in flight
    ISSUE(0, lb0, p00, p01, p02);
    ISSUE(1, lb1, p10, p11, p12);

    for (int j = 0; ; j += 2) {
        if (gw0 + j * NWSLOT >= NCHUNK) break;
        PROCESS(j, lb0, p00, p01, p02);
        ISSUE(j + 2, lb0, p00, p01, p02);

        if (gw0 + (j + 1) * NWSLOT >= NCHUNK) break;
        PROCESS(j + 1, lb1, p10, p11, p12);
        ISSUE(j + 3, lb1, p10, p11, p12);
    }

    // ---------------- block reduction -> unique global slots ----------------
    __syncthreads();               // all warps done with buffers; alias red/scr onto sm[0..]
    float* red = sm;               // 8*4*32 = 1024 floats
    float* scr = sm + 1024;        // 32 floats
    red[(wid * 4 + 0) * 32 + lane] = a1;
    red[(wid * 4 + 1) * 32 + lane] = h1;
    red[(wid * 4 + 2) * 32 + lane] = a2;
    red[(wid * 4 + 3) * 32 + lane] = h2;
    float cef = ce; float c1f = (float)c1, c2f = (float)c2;
    #pragma unroll
    for (int o = 16; o; o >>= 1) {
        cef += __shfl_xor_sync(0xffffffffu, cef, o);
        c1f += __shfl_xor_sync(0xffffffffu, c1f, o);
        c2f += __shfl_xor_sync(0xffffffffu, c2f, o);
    }
    if (lane == 0) { scr[wid] = cef; scr[8 + wid] = c1f; scr[16 + wid] = c2f; }
    __syncthreads();

    if (wid < 4) {
        float s = 0.f;
        #pragma unroll
        for (int w = 0; w < 8; w++) s += red[(w * 4 + wid) * 32 + lane];
        g_part[b][blockIdx.x][wid][lane] = s;
    }
    if (tid == 0) {
        float tce = 0.f, t1 = 0.f, t2 = 0.f;
        for (int w = 0; w < 8; w++) { tce += scr[w]; t1 += scr[8 + w]; t2 += scr[16 + w]; }
        g_misc[b][blockIdx.x][0] = tce;
        g_misc[b][blockIdx.x][1] = t1;
        g_misc[b][blockIdx.x][2] = t2;
    }

    // ---------------- last-CTA fused finalize ----------------
    __threadfence();
    __syncthreads();
    __shared__ unsigned int s_last;
    if (tid == 0) s_last = atomicInc(&g_sync, NBLK - 1);  // wraps to 0 each launch
    __syncthreads();
    if (s_last != NBLK - 1) return;
    __threadfence();

    float* part = scr;   // 16 floats of scratch
    for (int img = wid; img < BATCH; img += 8) {
        float s1 = 0.f, hh1 = 0.f, s2 = 0.f, hh2 = 0.f;
        float ceb = 0.f, cc1 = 0.f, cc2 = 0.f;
        #pragma unroll
        for (int x = 0; x < GX; x++) {
            s1  += g_part[img][x][0][lane];
            hh1 += g_part[img][x][1][lane];
            s2  += g_part[img][x][2][lane];
            hh2 += g_part[img][x][3][lane];
            ceb += g_misc[img][x][0];
            cc1 += g_misc[img][x][1];
            cc2 += g_misc[img][x][2];
        }
        float m1 = s1 / cc1, m2 = s2 / cc2;
        float A  = m1 * m1;
        float Bv = m2 * m2;
        float C  = m1 * m2;
        float D1 = m1 * hh1;
        float D2 = m2 * hh2;
        #pragma unroll
        for (int o = 16; o; o >>= 1) {
            A  += __shfl_xor_sync(0xffffffffu, A,  o);
            Bv += __shfl_xor_sync(0xffffffffu, Bv, o);
            C  += __shfl_xor_sync(0xffffffffu, C,  o);
            D1 += __shfl_xor_sync(0xffffffffu, D1, o);
            D2 += __shfl_xor_sync(0xffffffffu, D2, o);
        }
        if (lane == 0) {
            float n1 = fmaxf(sqrtf(A),  1e-12f);
            float n2 = fmaxf(sqrtf(Bv), 1e-12f);
            float intra = ((1.f - D1 / (n1 * cc1)) + (1.f - D2 / (n2 * cc2))) / (float)(NCLS - 1);
            float S11 = A  / (n1 * n1);
            float S22 = Bv / (n2 * n2);
            float S12 = C  / (n1 * n2);
            bool mk[NCLS][NCLS] = {};
            for (int r = 1; r < NCLS; r++) {
                for (int jn = 0; jn < 3; jn++) {
                    int n = nb[(img * NCLS + r) * 3 + jn];
                    if (n == 0) break;      // cumprod break semantics
                    mk[r][n] = true;        // scatter-max: duplicates count once
                }
            }
            float ssum = 0.f, msum = 0.f;
            for (int r = 1; r < NCLS; r++)
                for (int c = 0; c < NCLS; c++)
                    if (mk[r][c]) {
                        msum += 1.f;
                        float Sv = 0.f;
                        if (r == 1) Sv = (c == 1) ? S11 : ((c == 2) ? S12 : 0.f);
                        else        Sv = (c == 1) ? S12 : ((c == 2) ? S22 : 0.f);
                        ssum += Sv;
                    }
            part[img] = intra + ssum / msum + ceb * (1.0f / (float)HW);
        }
    }
    __syncthreads();
    if (tid == 0) {
        float tot = 0.f;
        #pragma unroll
        for (int i = 0; i < BATCH; i++) tot += part[i];
        out[0] = tot;
    }
}

extern "C" void kernel_launch(void* const* d_in, const int* in_sizes, int n_in,
                              void* d_out, int out_size) {
    const float* emb  = (const float*)d_in[0];
    const float* pred = (const float*)d_in[1];
    const int*   lab  = (const int*)d_in[2];
    const int*   nb   = (const int*)d_in[3];

    cudaFuncSetAttribute(main_kernel, cudaFuncAttributeMaxDynamicSharedMemorySize, SMEM_BYTES);

    main_kernel<<<dim3(GX, BATCH), 256, SMEM_BYTES>>>(emb, pred, lab, nb, (float*)d_out);
}

// round 7
// speedup vs baseline: 1.1658x; 1.1658x over previous
#include <cuda_runtime.h>

#define BATCH 16
#define ECH 32
#define NCLS 3
#define HW 262144           // 512*512
#define HW2 131072
#define WCHUNK 64           // pixels per warp-chunk
#define NCHUNK (HW/WCHUNK)  // 4096 chunks per image
#define GX 19               // grid (19,16) = 304 CTAs = exactly 2/SM on 152 SMs
#define NBLK (GX*BATCH)     // 304
#define NWSLOT (GX*8)       // 152 warp-slots per image
#define WROWS 68            // per-warp row stride (mod 32 == 4 -> conflict-free LDS.128)

// per-warp smem: vals [ECH][WROWS] + coeff [64] float4
#define VALS_FLOATS (ECH*WROWS)            // 2176
#define WARP_FLOATS (VALS_FLOATS + 256)    // 2432
#define SM_FLOATS (8*WARP_FLOATS)          // 19456
#define SMEM_BYTES (SM_FLOATS*4)           // 77824 -> 2 CTAs/SM (155.6 KB of 228)

// per-block partial results (unique slots -> no zeroing, no atomics on data)
__device__ float g_part[BATCH][GX][4][ECH]; // [0]=sum_emb_l1 [1]=sum_hat_l1 [2]=sum_emb_l2 [3]=sum_hat_l2
__device__ float g_misc[BATCH][GX][3];      // ce, c1, c2
__device__ unsigned int g_sync;             // zero-init; atomicInc wraps -> graph-replay safe

__global__ __launch_bounds__(256, 2)
void main_kernel(const float* __restrict__ emb,
                 const float* __restrict__ pred,
                 const int*  __restrict__ lab,
                 const int*  __restrict__ nb,
                 float* __restrict__ out) {
    extern __shared__ float sm[];

    const int b    = blockIdx.y;
    const int tid  = threadIdx.x;
    const int wid  = tid >> 5;
    const int lane = tid & 31;
    const int gw   = blockIdx.x * 8 + wid;     // global warp-slot in [0, NWSLOT)

    float*  valsW = sm + wid * WARP_FLOATS;                  // [ECH][WROWS]
    float4* coefW = (float4*)(valsW + VALS_FLOATS);          // [64] {i1, rn1, i2, rn2}

    const float2* emb2 = (const float2*)emb + (size_t)b * ECH  * HW2;
    const float2* pr2  = (const float2*)pred + (size_t)b * NCLS * HW2;
    const int2*   lb2  = (const int2*)lab + (size_t)b * HW2;

    // accumulators (lane == channel in phase B)
    float a1 = 0.f, h1 = 0.f, a2 = 0.f, h2 = 0.f;
    float ce = 0.f;
    int   cn1 = 0, cn2 = 0;

    // prefetch registers
    float2 v[ECH];
    int2   lp;
    float2 q0, q1, q2;

    // ---------------- prologue: load chunk gw, consume into warp buffer ----------------
    {
        const int qp = gw * 32 + lane;          // float2 (pixel-pair) index
        #pragma unroll
        for (int e = 0; e < ECH; e++) v[e] = emb2[e * HW2 + qp];
        lp = lb2[qp];
        q0 = pr2[qp]; q1 = pr2[HW2 + qp]; q2 = pr2[2 * HW2 + qp];

        float sx = 0.f, sy = 0.f;
        #pragma unroll
        for (int e = 0; e < ECH; e++) {
            float2 w = v[e];
            sx = fmaf(w.x, w.x, sx);
            sy = fmaf(w.y, w.y, sy);
            *(float2*)&valsW[e * WROWS + 2 * lane] = w;
        }
        float rx = 1.f / fmaxf(sqrtf(sx), 1e-8f);
        float ry = 1.f / fmaxf(sqrtf(sy), 1e-8f);
        coefW[2 * lane]     = make_float4((lp.x == 1) ? 1.f : 0.f, (lp.x == 1) ? rx : 0.f,
                                          (lp.x == 2) ? 1.f : 0.f, (lp.x == 2) ? rx : 0.f);
        coefW[2 * lane + 1] = make_float4((lp.y == 1) ? 1.f : 0.f, (lp.y == 1) ? ry : 0.f,
                                          (lp.y == 2) ? 1.f : 0.f, (lp.y == 2) ? ry : 0.f);
        cn1 += (lp.x == 1) + (lp.y == 1);
        cn2 += (lp.x == 2) + (lp.y == 2);
        float m   = fmaxf(q0.x, fmaxf(q1.x, q2.x));
        ce += m + __logf(__expf(q0.x - m) + __expf(q1.x - m) + __expf(q2.x - m))
              - ((lp.x == 0) ? q0.x : ((lp.x == 1) ? q1.x : q2.x));
        m = fmaxf(q0.y, fmaxf(q1.y, q2.y));
        ce += m + __logf(__expf(q0.y - m) + __expf(q1.y - m) + __expf(q2.y - m))
              - ((lp.y == 0) ? q0.y : ((lp.y == 1) ? q1.y : q2.y));
    }
    __syncwarp();

    // ---------------- warp-autonomous pipelined loop (NO block barriers) ----------------
    for (int i = 0; ; i++) {
        const int nidx = gw + (i + 1) * NWSLOT;
        const bool more = (nidx < NCHUNK);

        // issue next chunk's global loads (in flight across phase B)
        if (more) {
            const int qp = nidx * 32 + lane;
            #pragma unroll
            for (int e = 0; e < ECH; e++) v[e] = emb2[e * HW2 + qp];
            lp = lb2[qp];
            q0 = pr2[qp]; q1 = pr2[HW2 + qp]; q2 = pr2[2 * HW2 + qp];
        }

        // phase B: lane = channel, 64 px, all-FMAF with per-pixel coeff float4
        {
            const float* vrow = valsW + lane * WROWS;
            #pragma unroll 4
            for (int k = 0; k < 16; k++) {
                float4 w  = *(const float4*)(vrow + 4 * k);
                float4 c0 = coefW[4 * k + 0];    // broadcast
                float4 c1 = coefW[4 * k + 1];
                float4 c2 = coefW[4 * k + 2];
                float4 c3 = coefW[4 * k + 3];
                a1 = fmaf(w.x, c0.x, a1); h1 = fmaf(w.x, c0.y, h1);
                a2 = fmaf(w.x, c0.z, a2); h2 = fmaf(w.x, c0.w, h2);
                a1 = fmaf(w.y, c1.x, a1); h1 = fmaf(w.y, c1.y, h1);
                a2 = fmaf(w.y, c1.z, a2); h2 = fmaf(w.y, c1.w, h2);
                a1 = fmaf(w.z, c2.x, a1); h1 = fmaf(w.z, c2.y, h1);
                a2 = fmaf(w.z, c2.z, a2); h2 = fmaf(w.z, c2.w, h2);
                a1 = fmaf(w.w, c3.x, a1); h1 = fmaf(w.w, c3.y, h1);
                a2 = fmaf(w.w, c3.z, a2); h2 = fmaf(w.w, c3.w, h2);
            }
        }
        if (!more) break;
        __syncwarp();   // phase B reads done before overwrite

        // consume prefetched regs into own buffer
        {
            float sx = 0.f, sy = 0.f;
            #pragma unroll
            for (int e = 0; e < ECH; e++) {
                float2 w = v[e];
                sx = fmaf(w.x, w.x, sx);
                sy = fmaf(w.y, w.y, sy);
                *(float2*)&valsW[e * WROWS + 2 * lane] = w;
            }
            float rx = 1.f / fmaxf(sqrtf(sx), 1e-8f);
            float ry = 1.f / fmaxf(sqrtf(sy), 1e-8f);
            coefW[2 * lane]     = make_float4((lp.x == 1) ? 1.f : 0.f, (lp.x == 1) ? rx : 0.f,
                                              (lp.x == 2) ? 1.f : 0.f, (lp.x == 2) ? rx : 0.f);
            coefW[2 * lane + 1] = make_float4((lp.y == 1) ? 1.f : 0.f, (lp.y == 1) ? ry : 0.f,
                                              (lp.y == 2) ? 1.f : 0.f, (lp.y == 2) ? ry : 0.f);
            cn1 += (lp.x == 1) + (lp.y == 1);
            cn2 += (lp.x == 2) + (lp.y == 2);
            float m   = fmaxf(q0.x, fmaxf(q1.x, q2.x));
            ce += m + __logf(__expf(q0.x - m) + __expf(q1.x - m) + __expf(q2.x - m))
                  - ((lp.x == 0) ? q0.x : ((lp.x == 1) ? q1.x : q2.x));
            m = fmaxf(q0.y, fmaxf(q1.y, q2.y));
            ce += m + __logf(__expf(q0.y - m) + __expf(q1.y - m) + __expf(q2.y - m))
                  - ((lp.y == 0) ? q0.y : ((lp.y == 1) ? q1.y : q2.y));
        }
        __syncwarp();   // writes visible before next phase B
    }

    // ---------------- block reduction -> unique global slots ----------------
    __syncthreads();               // all warps done; alias red/scr onto sm[0..]
    float* red = sm;               // 8*4*32 = 1024 floats
    float* scr = sm + 1024;        // 32 floats
    red[(wid * 4 + 0) * 32 + lane] = a1;
    red[(wid * 4 + 1) * 32 + lane] = h1;
    red[(wid * 4 + 2) * 32 + lane] = a2;
    red[(wid * 4 + 3) * 32 + lane] = h2;
    float cef = ce; float c1f = (float)cn1, c2f = (float)cn2;
    #pragma unroll
    for (int o = 16; o; o >>= 1) {
        cef += __shfl_xor_sync(0xffffffffu, cef, o);
        c1f += __shfl_xor_sync(0xffffffffu, c1f, o);
        c2f += __shfl_xor_sync(0xffffffffu, c2f, o);
    }
    if (lane == 0) { scr[wid] = cef; scr[8 + wid] = c1f; scr[16 + wid] = c2f; }
    __syncthreads();

    if (wid < 4) {
        float s = 0.f;
        #pragma unroll
        for (int w = 0; w < 8; w++) s += red[(w * 4 + wid) * 32 + lane];
        g_part[b][blockIdx.x][wid][lane] = s;
    }
    if (tid == 0) {
        float tce = 0.f, t1 = 0.f, t2 = 0.f;
        for (int w = 0; w < 8; w++) { tce += scr[w]; t1 += scr[8 + w]; t2 += scr[16 + w]; }
        g_misc[b][blockIdx.x][0] = tce;
        g_misc[b][blockIdx.x][1] = t1;
        g_misc[b][blockIdx.x][2] = t2;
    }

    // ---------------- last-CTA fused finalize ----------------
    __threadfence();
    __syncthreads();
    __shared__ unsigned int s_last;
    if (tid == 0) s_last = atomicInc(&g_sync, NBLK - 1);  // wraps to 0 each launch
    __syncthreads();
    if (s_last != NBLK - 1) return;
    __threadfence();

    float* part = scr;   // 16 floats of scratch
    for (int img = wid; img < BATCH; img += 8) {
        float s1 = 0.f, hh1 = 0.f, s2 = 0.f, hh2 = 0.f;
        float ceb = 0.f, cc1 = 0.f, cc2 = 0.f;
        #pragma unroll
        for (int x = 0; x < GX; x++) {
            s1  += g_part[img][x][0][lane];
            hh1 += g_part[img][x][1][lane];
            s2  += g_part[img][x][2][lane];
            hh2 += g_part[img][x][3][lane];
            ceb += g_misc[img][x][0];
            cc1 += g_misc[img][x][1];
            cc2 += g_misc[img][x][2];
        }
        float m1 = s1 / cc1, m2 = s2 / cc2;
        float A  = m1 * m1;
        float Bv = m2 * m2;
        float C  = m1 * m2;
        float D1 = m1 * hh1;
        float D2 = m2 * hh2;
        #pragma unroll
        for (int o = 16; o; o >>= 1) {
            A  += __shfl_xor_sync(0xffffffffu, A,  o);
            Bv += __shfl_xor_sync(0xffffffffu, Bv, o);
            C  += __shfl_xor_sync(0xffffffffu, C,  o);
            D1 += __shfl_xor_sync(0xffffffffu, D1, o);
            D2 += __shfl_xor_sync(0xffffffffu, D2, o);
        }
        if (lane == 0) {
            float n1 = fmaxf(sqrtf(A),  1e-12f);
            float n2 = fmaxf(sqrtf(Bv), 1e-12f);
            float intra = ((1.f - D1 / (n1 * cc1)) + (1.f - D2 / (n2 * cc2))) / (float)(NCLS - 1);
            float S11 = A  / (n1 * n1);
            float S22 = Bv / (n2 * n2);
            float S12 = C  / (n1 * n2);
            bool mk[NCLS][NCLS] = {};
            for (int r = 1; r < NCLS; r++) {
                for (int j = 0; j < 3; j++) {
                    int n = nb[(img * NCLS + r) * 3 + j];
                    if (n == 0) break;      // cumprod break semantics
                    mk[r][n] = true;        // scatter-max: duplicates count once
                }
            }
            float ssum = 0.f, msum = 0.f;
            for (int r = 1; r < NCLS; r++)
                for (int c = 0; c < NCLS; c++)
                    if (mk[r][c]) {
                        msum += 1.f;
                        float Sv = 0.f;
                        if (r == 1) Sv = (c == 1) ? S11 : ((c == 2) ? S12 : 0.f);
                        else        Sv = (c == 1) ? S12 : ((c == 2) ? S22 : 0.f);
                        ssum += Sv;
                    }
            part[img] = intra + ssum / msum + ceb * (1.0f / (float)HW);
        }
    }
    __syncthreads();
    if (tid == 0) {
        float tot = 0.f;
        #pragma unroll
        for (int i = 0; i < BATCH; i++) tot += part[i];
        out[0] = tot;
    }
}

extern "C" void kernel_launch(void* const* d_in, const int* in_sizes, int n_in,
                              void* d_out, int out_size) {
    const float* emb  = (const float*)d_in[0];
    const float* pred = (const float*)d_in[1];
    const int*   lab  = (const int*)d_in[2];
    const int*   nb   = (const int*)d_in[3];

    cudaFuncSetAttribute(main_kernel, cudaFuncAttributeMaxDynamicSharedMemorySize, SMEM_BYTES);

    main_kernel<<<dim3(GX, BATCH), 256, SMEM_BYTES>>>(emb, pred, lab, nb, (float*)d_out);
}

// round 8
// speedup vs baseline: 1.1944x; 1.0246x over previous
#include <cuda_runtime.h>

#define BATCH 16
#define ECH 32
#define NCLS 3
#define HW 262144           // 512*512
#define HW2 131072
#define WCHUNK 64           // pixels per warp-chunk
#define NCHUNK (HW/WCHUNK)  // 4096 chunks per image
#define GX 19               // grid (19,16) = 304 CTAs = exactly 2/SM on 152 SMs
#define NBLK (GX*BATCH)     // 304
#define NWSLOT (GX*8)       // 152 warp-slots per image
#define WROWS 68            // per-warp row stride (mod 32 == 4 -> conflict-free LDS.128)

// shared memory layout (floats): 8 warp-private regions, then red/scr alias after loop
#define WREG (ECH*WROWS)               // 2176 floats per warp region
#define OFF_META (8*WREG)              // 17408
#define SM_FLOATS (OFF_META + 8*64)    // 17920
#define SMEM_BYTES (SM_FLOATS*4)       // 71680 -> 2 CTAs/SM

// per-block partial results (unique slots -> no zeroing, no atomics on data)
__device__ float g_part[BATCH][GX][4][ECH]; // [0]=sum_emb_l1 [1]=sum_hat_l1 [2]=sum_emb_l2 [3]=sum_hat_l2
__device__ float g_misc[BATCH][GX][3];      // ce, c1, c2
__device__ unsigned int g_sync;             // zero-init; atomicInc wraps -> graph-replay safe

__global__ __launch_bounds__(256, 2)
void main_kernel(const float* __restrict__ emb,
                 const float* __restrict__ pred,
                 const int*  __restrict__ lab,
                 const int*  __restrict__ nb,
                 float* __restrict__ out) {
    extern __shared__ float sm[];

    const int b    = blockIdx.y;
    const int tid  = threadIdx.x;
    const int wid  = tid >> 5;
    const int lane = tid & 31;
    const int gw   = blockIdx.x * 8 + wid;     // global warp-slot in [0, NWSLOT)

    float* valsW = sm + wid * WREG;            // [ECH][WROWS] warp-private
    float* metaW = sm + OFF_META + wid * 64;   // [64] warp-private

    const float2* emb2 = (const float2*)emb + (size_t)b * ECH  * HW2;
    const float2* pr2  = (const float2*)pred + (size_t)b * NCLS * HW2;
    const int2*   lb2  = (const int2*)lab + (size_t)b * HW2;

    // accumulators (lane == channel in phase B)
    float a1 = 0.f, h1 = 0.f, a2 = 0.f, h2 = 0.f;
    float ce = 0.f;
    int   c1 = 0, c2 = 0;

    // prefetch registers
    float2 v[ECH];
    int2   lp;
    float2 q0, q1, q2;

    // ---------------- prologue: load chunk gw, consume into warp buffer ----------------
    {
        const int qp = gw * 32 + lane;          // float2 (pixel-pair) index
        #pragma unroll
        for (int e = 0; e < ECH; e++) v[e] = emb2[e * HW2 + qp];
        lp = lb2[qp];
        q0 = pr2[qp]; q1 = pr2[HW2 + qp]; q2 = pr2[2 * HW2 + qp];

        float sx = 0.f, sy = 0.f;
        #pragma unroll
        for (int e = 0; e < ECH; e++) {
            float2 w = v[e];
            sx = fmaf(w.x, w.x, sx);
            sy = fmaf(w.y, w.y, sy);
            *(float2*)&valsW[e * WROWS + 2 * lane] = w;
        }
        float rx = 1.f / fmaxf(sqrtf(sx), 1e-8f);
        float ry = 1.f / fmaxf(sqrtf(sy), 1e-8f);
        *(float2*)&metaW[2 * lane] = make_float2(
            (lp.x == 1) ? rx : ((lp.x == 2) ? -rx : 0.f),
            (lp.y == 1) ? ry : ((lp.y == 2) ? -ry : 0.f));
        c1 += (lp.x == 1) + (lp.y == 1);
        c2 += (lp.x == 2) + (lp.y == 2);
        float m   = fmaxf(q0.x, fmaxf(q1.x, q2.x));
        ce += m + __logf(__expf(q0.x - m) + __expf(q1.x - m) + __expf(q2.x - m))
              - ((lp.x == 0) ? q0.x : ((lp.x == 1) ? q1.x : q2.x));
        m = fmaxf(q0.y, fmaxf(q1.y, q2.y));
        ce += m + __logf(__expf(q0.y - m) + __expf(q1.y - m) + __expf(q2.y - m))
              - ((lp.y == 0) ? q0.y : ((lp.y == 1) ? q1.y : q2.y));
    }
    __syncwarp();

    // ---------------- warp-autonomous pipelined loop (NO block barriers) ----------------
    for (int i = 0; ; i++) {
        const int nidx = gw + (i + 1) * NWSLOT;
        const bool more = (nidx < NCHUNK);

        // issue next chunk's global loads (in flight across phase B)
        if (more) {
            const int qp = nidx * 32 + lane;
            #pragma unroll
            for (int e = 0; e < ECH; e++) v[e] = emb2[e * HW2 + qp];
            lp = lb2[qp];
            q0 = pr2[qp]; q1 = pr2[HW2 + qp]; q2 = pr2[2 * HW2 + qp];
        }

        // phase B: lane = channel, 64 px via 16 float4 reads (conflict-free, WROWS%32==4)
        {
            const float* vrow = valsW + lane * WROWS;
            #pragma unroll 4
            for (int k = 0; k < 16; k++) {
                float4 w = *(const float4*)(vrow + 4 * k);
                float4 t = *(const float4*)(metaW + 4 * k);   // broadcast within warp
                float vh0 = w.x * fabsf(t.x);
                float vh1 = w.y * fabsf(t.y);
                float vh2 = w.z * fabsf(t.z);
                float vh3 = w.w * fabsf(t.w);
                if      (t.x > 0.f) { a1 += w.x; h1 += vh0; }
                else if (t.x < 0.f) { a2 += w.x; h2 += vh0; }
                if      (t.y > 0.f) { a1 += w.y; h1 += vh1; }
                else if (t.y < 0.f) { a2 += w.y; h2 += vh1; }
                if      (t.z > 0.f) { a1 += w.z; h1 += vh2; }
                else if (t.z < 0.f) { a2 += w.z; h2 += vh2; }
                if      (t.w > 0.f) { a1 += w.w; h1 += vh3; }
                else if (t.w < 0.f) { a2 += w.w; h2 += vh3; }
            }
        }
        if (!more) break;
        __syncwarp();   // phase B reads done before overwrite

        // consume prefetched regs into own buffer
        {
            float sx = 0.f, sy = 0.f;
            #pragma unroll
            for (int e = 0; e < ECH; e++) {
                float2 w = v[e];
                sx = fmaf(w.x, w.x, sx);
                sy = fmaf(w.y, w.y, sy);
                *(float2*)&valsW[e * WROWS + 2 * lane] = w;
            }
            float rx = 1.f / fmaxf(sqrtf(sx), 1e-8f);
            float ry = 1.f / fmaxf(sqrtf(sy), 1e-8f);
            *(float2*)&metaW[2 * lane] = make_float2(
                (lp.x == 1) ? rx : ((lp.x == 2) ? -rx : 0.f),
                (lp.y == 1) ? ry : ((lp.y == 2) ? -ry : 0.f));
            c1 += (lp.x == 1) + (lp.y == 1);
            c2 += (lp.x == 2) + (lp.y == 2);
            float m   = fmaxf(q0.x, fmaxf(q1.x, q2.x));
            ce += m + __logf(__expf(q0.x - m) + __expf(q1.x - m) + __expf(q2.x - m))
                  - ((lp.x == 0) ? q0.x : ((lp.x == 1) ? q1.x : q2.x));
            m = fmaxf(q0.y, fmaxf(q1.y, q2.y));
            ce += m + __logf(__expf(q0.y - m) + __expf(q1.y - m) + __expf(q2.y - m))
                  - ((lp.y == 0) ? q0.y : ((lp.y == 1) ? q1.y : q2.y));
        }
        __syncwarp();   // writes visible before next phase B
    }

    // ---------------- block reduction -> unique global slots ----------------
    __syncthreads();               // all warps done with buffers; alias red/scr onto sm[0..]
    float* red = sm;               // 8*4*32 = 1024 floats
    float* scr = sm + 1024;        // 32 floats
    red[(wid * 4 + 0) * 32 + lane] = a1;
    red[(wid * 4 + 1) * 32 + lane] = h1;
    red[(wid * 4 + 2) * 32 + lane] = a2;
    red[(wid * 4 + 3) * 32 + lane] = h2;
    float cef = ce; float c1f = (float)c1, c2f = (float)c2;
    #pragma unroll
    for (int o = 16; o; o >>= 1) {
        cef += __shfl_xor_sync(0xffffffffu, cef, o);
        c1f += __shfl_xor_sync(0xffffffffu, c1f, o);
        c2f += __shfl_xor_sync(0xffffffffu, c2f, o);
    }
    if (lane == 0) { scr[wid] = cef; scr[8 + wid] = c1f; scr[16 + wid] = c2f; }
    __syncthreads();

    if (wid < 4) {
        float s = 0.f;
        #pragma unroll
        for (int w = 0; w < 8; w++) s += red[(w * 4 + wid) * 32 + lane];
        g_part[b][blockIdx.x][wid][lane] = s;
    }
    if (tid == 0) {
        float tce = 0.f, t1 = 0.f, t2 = 0.f;
        for (int w = 0; w < 8; w++) { tce += scr[w]; t1 += scr[8 + w]; t2 += scr[16 + w]; }
        g_misc[b][blockIdx.x][0] = tce;
        g_misc[b][blockIdx.x][1] = t1;
        g_misc[b][blockIdx.x][2] = t2;
    }

    // ---------------- last-CTA fused finalize ----------------
    __threadfence();
    __syncthreads();
    __shared__ unsigned int s_last;
    if (tid == 0) s_last = atomicInc(&g_sync, NBLK - 1);  // wraps to 0 each launch
    __syncthreads();
    if (s_last != NBLK - 1) return;
    __threadfence();

    float* part = scr;   // 16 floats of scratch
    for (int img = wid; img < BATCH; img += 8) {
        float s1 = 0.f, hh1 = 0.f, s2 = 0.f, hh2 = 0.f;
        float ceb = 0.f, cc1 = 0.f, cc2 = 0.f;
        #pragma unroll
        for (int x = 0; x < GX; x++) {
            s1  += g_part[img][x][0][lane];
            hh1 += g_part[img][x][1][lane];
            s2  += g_part[img][x][2][lane];
            hh2 += g_part[img][x][3][lane];
            ceb += g_misc[img][x][0];
            cc1 += g_misc[img][x][1];
            cc2 += g_misc[img][x][2];
        }
        float m1 = s1 / cc1, m2 = s2 / cc2;
        float A  = m1 * m1;
        float Bv = m2 * m2;
        float C  = m1 * m2;
        float D1 = m1 * hh1;
        float D2 = m2 * hh2;
        #pragma unroll
        for (int o = 16; o; o >>= 1) {
            A  += __shfl_xor_sync(0xffffffffu, A,  o);
            Bv += __shfl_xor_sync(0xffffffffu, Bv, o);
            C  += __shfl_xor_sync(0xffffffffu, C,  o);
            D1 += __shfl_xor_sync(0xffffffffu, D1, o);
            D2 += __shfl_xor_sync(0xffffffffu, D2, o);
        }
        if (lane == 0) {
            float n1 = fmaxf(sqrtf(A),  1e-12f);
            float n2 = fmaxf(sqrtf(Bv), 1e-12f);
            float intra = ((1.f - D1 / (n1 * cc1)) + (1.f - D2 / (n2 * cc2))) / (float)(NCLS - 1);
            float S11 = A  / (n1 * n1);
            float S22 = Bv / (n2 * n2);
            float S12 = C  / (n1 * n2);
            bool mk[NCLS][NCLS] = {};
            for (int r = 1; r < NCLS; r++) {
                for (int j = 0; j < 3; j++) {
                    int n = nb[(img * NCLS + r) * 3 + j];
                    if (n == 0) break;      // cumprod break semantics
                    mk[r][n] = true;        // scatter-max: duplicates count once
                }
            }
            float ssum = 0.f, msum = 0.f;
            for (int r = 1; r < NCLS; r++)
                for (int c = 0; c < NCLS; c++)
                    if (mk[r][c]) {
                        msum += 1.f;
                        float Sv = 0.f;
                        if (r == 1) Sv = (c == 1) ? S11 : ((c == 2) ? S12 : 0.f);
                        else        Sv = (c == 1) ? S12 : ((c == 2) ? S22 : 0.f);
                        ssum += Sv;
                    }
            part[img] = intra + ssum / msum + ceb * (1.0f / (float)HW);
        }
    }
    __syncthreads();
    if (tid == 0) {
        float tot = 0.f;
        #pragma unroll
        for (int i = 0; i < BATCH; i++) tot += part[i];
        out[0] = tot;
    }
}

extern "C" void kernel_launch(void* const* d_in, const int* in_sizes, int n_in,
                              void* d_out, int out_size) {
    const float* emb  = (const float*)d_in[0];
    const float* pred = (const float*)d_in[1];
    const int*   lab  = (const int*)d_in[2];
    const int*   nb   = (const int*)d_in[3];

    cudaFuncSetAttribute(main_kernel, cudaFuncAttributeMaxDynamicSharedMemorySize, SMEM_BYTES);

    main_kernel<<<dim3(GX, BATCH), 256, SMEM_BYTES>>>(emb, pred, lab, nb, (float*)d_out);
}